// round 7
// baseline (speedup 1.0000x reference)
#include <cuda_runtime.h>
#include <cuda_bf16.h>
#include <cstdint>

#define BB 128
#define TT 1024
#define DD 128
#define CC 384
#define TILE 64                   // rows per work CTA
#define NE_BLK 64                 // E-setup CTAs

// ---- smem byte offsets ----
#define S_MS 0                    // 512 B mean
#define S_A  512                  // 16 KB  Ahi = bf16(V)   (aliased by phase-A scratch)
#define S_AL (S_A + 16384)        // 16 KB  Alo = bf16(V - hi)
#define S_TOTAL (S_AL + 16384)    // 33280 B

// ---- device scratch (overwritten/reset every launch -> deterministic) ----
__device__ float g_partial[BB * 16 * DD];
__device__ __align__(16) unsigned char g_E[32768];   // bf16 E[n][k], 256 B rows
__device__ unsigned g_sync[256];  // [0..127] per-batch counters, [128] = E count

// swizzled offset inside a [rows][128] bf16 tile with 256B rows
__device__ __forceinline__ uint32_t tile_off(int r, int k) {
    return (uint32_t)r * 256u + ((((uint32_t)k >> 3) ^ ((uint32_t)r & 7u)) << 4)
         + ((uint32_t)k & 7u) * 2u;
}

__device__ __forceinline__ uint32_t smem_u32(const void* p) {
    uint32_t a;
    asm("{ .reg .u64 t; cvta.to.shared.u64 t, %1; cvt.u32.u64 %0, t; }"
        : "=r"(a) : "l"(p));
    return a;
}
__device__ __forceinline__ unsigned ld_acq(const unsigned* p) {
    unsigned v;
    asm volatile("ld.acquire.gpu.global.u32 %0, [%1];" : "=r"(v) : "l"(p) : "memory");
    return v;
}

#define LDMATRIX_X4(r0, r1, r2, r3, addr)                                      \
    asm volatile("ldmatrix.sync.aligned.m8n8.x4.shared.b16 {%0,%1,%2,%3}, [%4];" \
        : "=r"(r0), "=r"(r1), "=r"(r2), "=r"(r3) : "r"(addr))

#define MMA_BF16(d, a0, a1, a2, a3, b0, b1)                                    \
    asm volatile("mma.sync.aligned.m16n8k16.row.col.f32.bf16.bf16.f32 "        \
        "{%0,%1,%2,%3}, {%4,%5,%6,%7}, {%8,%9}, {%0,%1,%2,%3};"                \
        : "+f"((d)[0]), "+f"((d)[1]), "+f"((d)[2]), "+f"((d)[3])               \
        : "r"(a0), "r"(a1), "r"(a2), "r"(a3), "r"(b0), "r"(b1))

__device__ __forceinline__ float2 bfx2f(uint32_t u) {
    return __bfloat1622float2(*reinterpret_cast<__nv_bfloat162*>(&u));
}

// ---------------------------------------------------------------------------
// Single fused kernel. bids [0,64): E setup. bids [64, 64+2048): work CTAs.
// ---------------------------------------------------------------------------
__global__ __launch_bounds__(256, 4)
void crosschan_fused_kernel(const float* __restrict__ x,
                            const float* __restrict__ kern,
                            float* __restrict__ out)
{
    extern __shared__ char smem[];
    const uint32_t sbase = smem_u32(smem);
    const int tid = threadIdx.x;

    // ------------------------- E setup CTAs --------------------------
    if (blockIdx.x < NE_BLK) {
        int idx = blockIdx.x * 256 + tid;          // 16384 elements
        int n = idx >> 7, k = idx & 127;
        float v = kern[k * DD + n] - (n == k ? 1.0f : 0.0f);
        *(__nv_bfloat16*)(g_E + n * 256 + k * 2) = __float2bfloat16(v);
        __threadfence();
        __syncthreads();
        if (tid == 0) atomicAdd(&g_sync[128], 1u);
        return;
    }

    const int wb   = blockIdx.x - NE_BLK;          // work id 0..2047
    const int b    = wb >> 4;                      // batch
    const int wid  = tid >> 5;
    const int lane = tid & 31;
    float* Ms = (float*)(smem + S_MS);
    float* Pt = (float*)(smem + S_A);              // phase-A scratch

    // ---------------- Phase A: partial column sums of y ----------------
    {
        const int d = tid & 127, half = tid >> 7;
        const float* p = x + ((size_t)(wb * TILE + half * 32)) * CC + d;
        float acc = 0.f;
#pragma unroll
        for (int t = 0; t < 32; ++t) acc += p[(size_t)t * CC];
        Pt[tid] = acc;
    }
    __syncthreads();
    if (tid < 128)
        g_partial[wb * DD + tid] = Pt[tid] + Pt[tid + 128];
    __threadfence();
    __syncthreads();
    if (tid == 0) atomicAdd(&g_sync[b], 1u);

    // ---------------- spin: batch partials + E ready ----------------
    if (tid == 0) {
        while (ld_acq(&g_sync[128]) < (unsigned)NE_BLK) __nanosleep(64);
        while (ld_acq(&g_sync[b]) < 16u) __nanosleep(64);
    }
    __syncthreads();

    // mean reduce (128 threads, L2-hot partials)
    if (tid < DD) {
        float m = 0.f;
#pragma unroll
        for (int s = 0; s < 16; ++s) m += g_partial[(b * 16 + s) * DD + tid];
        Ms[tid] = m * (1.0f / (float)TT);
    }
    __syncthreads();

    // ------------------------------------------------------------------
    // Phase 1: softmax + intensity + V as bf16 hi/lo tiles (y re-read: L2)
    // ------------------------------------------------------------------
    {
        const int l = tid & 7;
#pragma unroll
        for (int pass = 0; pass < 2; ++pass) {
            const int r = pass * 32 + (tid >> 3);
            const size_t rowbase = ((size_t)(wb * TILE + r)) * CC;
            const float4* xr = (const float4*)(x + rowbase);
            float4* o4 = (float4*)(out + rowbase);

            float4 w4[4], y4[4];
#pragma unroll
            for (int i = 0; i < 4; ++i) {
                y4[i] = xr[l * 4 + i];
                w4[i] = xr[32 + l * 4 + i];
            }
            float ex[16], s = 0.f;
#pragma unroll
            for (int i = 0; i < 4; ++i) {
                ex[4*i+0] = __expf(w4[i].x); ex[4*i+1] = __expf(w4[i].y);
                ex[4*i+2] = __expf(w4[i].z); ex[4*i+3] = __expf(w4[i].w);
                s += ex[4*i+0] + ex[4*i+1] + ex[4*i+2] + ex[4*i+3];
            }
            s += __shfl_xor_sync(0xffffffffu, s, 1);
            s += __shfl_xor_sync(0xffffffffu, s, 2);
            s += __shfl_xor_sync(0xffffffffu, s, 4);
            const float inv = 1.0f / s;

#pragma unroll
            for (int h = 0; h < 2; ++h) {
                float v[8];
#pragma unroll
                for (int i = 0; i < 2; ++i) {
                    const int ii = h * 2 + i;
                    const int c0 = l * 16 + ii * 4;
                    float4 ev = make_float4(ex[4*ii+0], ex[4*ii+1],
                                            ex[4*ii+2], ex[4*ii+3]);
                    o4[32 + l * 4 + ii] = ev;    // intensity = exp(w)
                    v[4*i+0] = ev.x * inv * (y4[ii].x - Ms[c0 + 0]);
                    v[4*i+1] = ev.y * inv * (y4[ii].y - Ms[c0 + 1]);
                    v[4*i+2] = ev.z * inv * (y4[ii].z - Ms[c0 + 2]);
                    v[4*i+3] = ev.w * inv * (y4[ii].w - Ms[c0 + 3]);
                }
                uint32_t ph[4], pl[4];
#pragma unroll
                for (int j = 0; j < 4; ++j) {
                    float a = v[2*j], c = v[2*j+1];
                    __nv_bfloat162 th = __floats2bfloat162_rn(a, c);
                    float2 back = __bfloat1622float2(th);
                    __nv_bfloat162 tl = __floats2bfloat162_rn(a - back.x,
                                                              c - back.y);
                    ph[j] = *reinterpret_cast<uint32_t*>(&th);
                    pl[j] = *reinterpret_cast<uint32_t*>(&tl);
                }
                uint32_t off = tile_off(r, l * 16 + h * 8);
                *(uint4*)(smem + S_A  + off) = make_uint4(ph[0], ph[1], ph[2], ph[3]);
                *(uint4*)(smem + S_AL + off) = make_uint4(pl[0], pl[1], pl[2], pl[3]);
            }
        }
    }
    __syncthreads();

    // ------------------------------------------------------------------
    // Phase 2: V@E, A-frags via ldmatrix (smem), B-frags via LDG (L1-hot E)
    // Warp: rows m0..m0+15, cols nb..nb+63 (8 n-blocks of 8).
    // ------------------------------------------------------------------
    const int m0 = (wid >> 1) * 16;
    const int nb = (wid & 1) * 64;

    float acc[8][4];
#pragma unroll
    for (int i = 0; i < 8; ++i)
#pragma unroll
        for (int j = 0; j < 4; ++j) acc[i][j] = 0.f;

    const int aRow = m0 + (lane & 7) + (lane & 8);
    const uint32_t aBase = sbase + S_A + aRow * 256;
    const uint32_t aXor  = (uint32_t)(aRow & 7) << 4;
    const uint32_t aSel  = (uint32_t)(lane >> 4);
    // per-lane E base: n = nb + j*8 + lane/4, byte = n*256 + (lane&3)*4 + ks*32
    const unsigned char* eLane = g_E + (nb + (lane >> 2)) * 256 + (lane & 3) * 4;

#pragma unroll
    for (int ks = 0; ks < 8; ++ks) {
        uint32_t a0, a1, a2, a3;
        LDMATRIX_X4(a0, a1, a2, a3,
                    aBase + ((((2u * ks + aSel) << 4) ^ aXor)));
        const unsigned char* ek = eLane + ks * 32;
#pragma unroll
        for (int j = 0; j < 8; ++j) {
            uint32_t b0 = __ldg((const uint32_t*)(ek + j * 2048));
            uint32_t b1 = __ldg((const uint32_t*)(ek + j * 2048 + 16));
            MMA_BF16(acc[j], a0, a1, a2, a3, b0, b1);
        }
    }

    // ------------------------------------------------------------------
    // Phase 3: fold + epilogue in fragment layout (no smem exchange).
    // Quad lanes cover 8 contiguous floats per row -> full 32B sectors.
    // ------------------------------------------------------------------
    {
        const int r1 = m0 + (lane >> 2);
        const int r2 = r1 + 8;
        const size_t rb1 = ((size_t)(wb * TILE + r1)) * CC;
        const size_t rb2 = ((size_t)(wb * TILE + r2)) * CC;
#pragma unroll
        for (int nt = 0; nt < 8; ++nt) {
            const int c = nb + nt * 8 + 2 * (lane & 3);
            const uint32_t o1 = tile_off(r1, c), o2 = tile_off(r2, c);
            float2 yo1 = *(const float2*)(x + rb1 + 2 * DD + c);
            float2 yo2 = *(const float2*)(x + rb2 + 2 * DD + c);
            float2 h1 = bfx2f(*(uint32_t*)(smem + S_A  + o1));
            float2 l1 = bfx2f(*(uint32_t*)(smem + S_AL + o1));
            float2 h2 = bfx2f(*(uint32_t*)(smem + S_A  + o2));
            float2 l2 = bfx2f(*(uint32_t*)(smem + S_AL + o2));
            const float mc0 = Ms[c], mc1 = Ms[c + 1];
            float2 s1 = make_float2(acc[nt][0] + h1.x + l1.x + mc0,
                                    acc[nt][1] + h1.y + l1.y + mc1);
            float2 s2 = make_float2(acc[nt][2] + h2.x + l2.x + mc0,
                                    acc[nt][3] + h2.y + l2.y + mc1);
            *(float2*)(out + rb1 + c) = s1;
            *(float2*)(out + rb2 + c) = s2;
            *(float2*)(out + rb1 + 2 * DD + c) =
                make_float2(yo1.x - s1.x, yo1.y - s1.y);
            *(float2*)(out + rb2 + 2 * DD + c) =
                make_float2(yo2.x - s2.x, yo2.y - s2.y);
        }
    }
}

// ---------------------------------------------------------------------------
extern "C" void kernel_launch(void* const* d_in, const int* in_sizes, int n_in,
                              void* d_out, int out_size) {
    const float* x    = (const float*)d_in[0];
    const float* kern = (const float*)d_in[1];
    float* out        = (float*)d_out;

    void* syncp = nullptr;
    cudaGetSymbolAddress(&syncp, g_sync);
    cudaMemsetAsync(syncp, 0, 256 * sizeof(unsigned), 0);

    cudaFuncSetAttribute(crosschan_fused_kernel,
                         cudaFuncAttributeMaxDynamicSharedMemorySize, S_TOTAL);
    crosschan_fused_kernel<<<NE_BLK + BB * (TT / TILE), 256, S_TOTAL>>>(x, kern, out);
}

// round 8
// speedup vs baseline: 1.4422x; 1.4422x over previous
#include <cuda_runtime.h>
#include <cuda_bf16.h>
#include <cstdint>

#define BB 128
#define TT 1024
#define DD 128
#define CC 384
#define TILE 64                   // rows per work CTA
#define NE_BLK 64                 // E-setup CTAs

// ---- smem byte offsets ----
#define S_MS 0                    // 512 B mean
#define S_E  512                  // 32 KB E (bf16, swizzled); aliased by Dbuf
#define S_A  (S_E + 34816)        // 16 KB  Ahi = bf16(V)  (phase-A scratch alias)
#define S_AL (S_A + 16384)        // 16 KB  Alo = bf16(V - hi)
#define S_TOTAL (S_AL + 16384)    // 68096 B
#define DPAD 136                  // Dbuf row pitch in floats

// ---- device scratch (overwritten/reset every launch -> deterministic) ----
__device__ float g_partial[BB * 16 * DD];
__device__ __align__(16) unsigned char g_E[32768];
__device__ unsigned g_sync[256];  // [0..127] per-batch counters, [128] = E count

// swizzled offset inside a [rows][128] bf16 tile with 256B rows
__device__ __forceinline__ uint32_t tile_off(int r, int k) {
    return (uint32_t)r * 256u + ((((uint32_t)k >> 3) ^ ((uint32_t)r & 7u)) << 4)
         + ((uint32_t)k & 7u) * 2u;
}

__device__ __forceinline__ uint32_t smem_u32(const void* p) {
    uint32_t a;
    asm("{ .reg .u64 t; cvta.to.shared.u64 t, %1; cvt.u32.u64 %0, t; }"
        : "=r"(a) : "l"(p));
    return a;
}
__device__ __forceinline__ unsigned ld_acq(const unsigned* p) {
    unsigned v;
    asm volatile("ld.acquire.gpu.global.u32 %0, [%1];" : "=r"(v) : "l"(p) : "memory");
    return v;
}

#define LDMATRIX_X4(r0, r1, r2, r3, addr)                                      \
    asm volatile("ldmatrix.sync.aligned.m8n8.x4.shared.b16 {%0,%1,%2,%3}, [%4];" \
        : "=r"(r0), "=r"(r1), "=r"(r2), "=r"(r3) : "r"(addr))

#define MMA_BF16(d, a0, a1, a2, a3, b0, b1)                                    \
    asm volatile("mma.sync.aligned.m16n8k16.row.col.f32.bf16.bf16.f32 "        \
        "{%0,%1,%2,%3}, {%4,%5,%6,%7}, {%8,%9}, {%0,%1,%2,%3};"                \
        : "+f"((d)[0]), "+f"((d)[1]), "+f"((d)[2]), "+f"((d)[3])               \
        : "r"(a0), "r"(a1), "r"(a2), "r"(a3), "r"(b0), "r"(b1))

#define CP_ASYNC16(saddr, gaddr)                                               \
    asm volatile("cp.async.cg.shared.global [%0], [%1], 16;"                   \
        :: "r"(saddr), "l"(gaddr) : "memory")
#define CP_COMMIT() asm volatile("cp.async.commit_group;" ::: "memory")
#define CP_WAIT0()  asm volatile("cp.async.wait_group 0;" ::: "memory")

__device__ __forceinline__ float2 bfx2f(uint32_t u) {
    return __bfloat1622float2(*reinterpret_cast<__nv_bfloat162*>(&u));
}

// ---------------------------------------------------------------------------
// Single fused kernel. bids [0,64): E setup. bids [64, 64+2048): work CTAs.
// ---------------------------------------------------------------------------
__global__ __launch_bounds__(256, 2)
void crosschan_fused_kernel(const float* __restrict__ x,
                            const float* __restrict__ kern,
                            float* __restrict__ out)
{
    extern __shared__ char smem[];
    const uint32_t sbase = smem_u32(smem);
    const int tid = threadIdx.x;

    // ------------------------- E setup CTAs --------------------------
    if (blockIdx.x < NE_BLK) {
        int idx = blockIdx.x * 256 + tid;          // 16384 elements
        int n = idx >> 7, k = idx & 127;
        float v = kern[k * DD + n] - (n == k ? 1.0f : 0.0f);
        *(__nv_bfloat16*)(g_E + tile_off(n, k)) = __float2bfloat16(v);
        __threadfence();
        __syncthreads();
        if (tid == 0) atomicAdd(&g_sync[128], 1u);
        return;
    }

    const int wb   = blockIdx.x - NE_BLK;          // work id 0..2047
    const int b    = wb >> 4;                      // batch
    const int wid  = tid >> 5;
    const int lane = tid & 31;
    float* Ms = (float*)(smem + S_MS);
    float* Db = (float*)(smem + S_E);              // Dbuf aliases E after MMA
    float* Pt = (float*)(smem + S_A);              // phase-A scratch [8][128]

    // ---------------- Phase A: column sums of y (8 LDG.128/thread) -----
    {
        const int r0 = wid * 8;                    // warp sums 8 rows
        const float4* yb = (const float4*)(x + ((size_t)(wb * TILE + r0)) * CC) + lane;
        float4 t[8];
#pragma unroll
        for (int i = 0; i < 8; ++i) t[i] = yb[(size_t)i * (CC / 4)];
        float4 s4 = make_float4(0.f, 0.f, 0.f, 0.f);
#pragma unroll
        for (int i = 0; i < 8; ++i) {
            s4.x += t[i].x; s4.y += t[i].y; s4.z += t[i].z; s4.w += t[i].w;
        }
        ((float4*)Pt)[wid * 32 + lane] = s4;
    }
    __syncthreads();
    if (tid < 128) {
        float m = 0.f;
#pragma unroll
        for (int w = 0; w < 8; ++w) m += Pt[w * 128 + tid];
        g_partial[wb * DD + tid] = m;
    }
    __threadfence();
    __syncthreads();
    if (tid == 0) atomicAdd(&g_sync[b], 1u);

    // -------- hoist ALL phase-1 x loads (independent of mean) ---------
    const int l  = tid & 7;
    const int rr = tid >> 3;                       // row within 32-row chunk
    float4 y4h[2][4], w4h[2][4];
#pragma unroll
    for (int p = 0; p < 2; ++p) {
        const float4* xr = (const float4*)(x + ((size_t)(wb * TILE + p * 32 + rr)) * CC);
#pragma unroll
        for (int i = 0; i < 4; ++i) {
            y4h[p][i] = xr[l * 4 + i];
            w4h[p][i] = xr[32 + l * 4 + i];
        }
    }

    // ---------------- spin: batch partials + E ready ----------------
    if (tid == 0) {
        while (ld_acq(&g_sync[128]) < (unsigned)NE_BLK) __nanosleep(64);
        while (ld_acq(&g_sync[b]) < 16u) __nanosleep(64);
    }
    __syncthreads();

    // async E copy: issue now, wait after phase 1
    {
        const char* eg = (const char*)g_E;
#pragma unroll
        for (int i = 0; i < 8; ++i) {
            uint32_t off = (uint32_t)(tid + i * 256) * 16u;
            CP_ASYNC16(sbase + S_E + off, eg + off);
        }
        CP_COMMIT();
    }

    // mean reduce (128 threads, L2-hot partials)
    if (tid < DD) {
        float m = 0.f;
#pragma unroll
        for (int s = 0; s < 16; ++s) m += g_partial[(b * 16 + s) * DD + tid];
        Ms[tid] = m * (1.0f / (float)TT);
    }
    __syncthreads();

    // ------------------------------------------------------------------
    // Phase 1: softmax + intensity + V as bf16 hi/lo tiles (loads in regs)
    // ------------------------------------------------------------------
#pragma unroll
    for (int p = 0; p < 2; ++p) {
        const int r = p * 32 + rr;
        const size_t rowbase = ((size_t)(wb * TILE + r)) * CC;
        float4* o4 = (float4*)(out + rowbase);

        float ex[16], s = 0.f;
#pragma unroll
        for (int i = 0; i < 4; ++i) {
            ex[4*i+0] = __expf(w4h[p][i].x); ex[4*i+1] = __expf(w4h[p][i].y);
            ex[4*i+2] = __expf(w4h[p][i].z); ex[4*i+3] = __expf(w4h[p][i].w);
            s += ex[4*i+0] + ex[4*i+1] + ex[4*i+2] + ex[4*i+3];
        }
        s += __shfl_xor_sync(0xffffffffu, s, 1);
        s += __shfl_xor_sync(0xffffffffu, s, 2);
        s += __shfl_xor_sync(0xffffffffu, s, 4);
        const float inv = 1.0f / s;

#pragma unroll
        for (int h = 0; h < 2; ++h) {
            float v[8];
#pragma unroll
            for (int i = 0; i < 2; ++i) {
                const int ii = h * 2 + i;
                const int c0 = l * 16 + ii * 4;
                float4 ev = make_float4(ex[4*ii+0], ex[4*ii+1],
                                        ex[4*ii+2], ex[4*ii+3]);
                o4[32 + l * 4 + ii] = ev;          // intensity = exp(w)
                v[4*i+0] = ev.x * inv * (y4h[p][ii].x - Ms[c0 + 0]);
                v[4*i+1] = ev.y * inv * (y4h[p][ii].y - Ms[c0 + 1]);
                v[4*i+2] = ev.z * inv * (y4h[p][ii].z - Ms[c0 + 2]);
                v[4*i+3] = ev.w * inv * (y4h[p][ii].w - Ms[c0 + 3]);
            }
            uint32_t ph[4], pl[4];
#pragma unroll
            for (int j = 0; j < 4; ++j) {
                float a = v[2*j], c = v[2*j+1];
                __nv_bfloat162 th = __floats2bfloat162_rn(a, c);
                float2 back = __bfloat1622float2(th);
                __nv_bfloat162 tl = __floats2bfloat162_rn(a - back.x, c - back.y);
                ph[j] = *reinterpret_cast<uint32_t*>(&th);
                pl[j] = *reinterpret_cast<uint32_t*>(&tl);
            }
            uint32_t off = tile_off(r, l * 16 + h * 8);
            *(uint4*)(smem + S_A  + off) = make_uint4(ph[0], ph[1], ph[2], ph[3]);
            *(uint4*)(smem + S_AL + off) = make_uint4(pl[0], pl[1], pl[2], pl[3]);
        }
    }
    CP_WAIT0();
    __syncthreads();

    // ------------------------------------------------------------------
    // Prefetch y_obs for the epilogue (lands during MMA + fold)
    // ------------------------------------------------------------------
    float4 yo[8];
#pragma unroll
    for (int it = 0; it < 8; ++it) {
        const int r = it * 8 + wid;
        const size_t base = ((size_t)(wb * TILE + r)) * CC;
        yo[it] = ((const float4*)(x + base + 2 * DD))[lane];
    }

    // ------------------------------------------------------------------
    // Phase 2: V@E via bf16 mma.sync (A hi from smem, E from smem)
    // ------------------------------------------------------------------
    const int m0 = (wid >> 1) * 16;
    const int nb = (wid & 1) * 64;

    float acc[8][4];
#pragma unroll
    for (int i = 0; i < 8; ++i)
#pragma unroll
        for (int j = 0; j < 4; ++j) acc[i][j] = 0.f;

    const int aRow = m0 + (lane & 7) + (lane & 8);
    const uint32_t aBase = sbase + S_A + aRow * 256;
    const uint32_t aXor  = (uint32_t)(aRow & 7) << 4;
    const uint32_t aSel  = (uint32_t)(lane >> 4);
    const int bRowOff = (lane & 7) + ((lane >> 4) << 3);
    const uint32_t bSel = (uint32_t)((lane >> 3) & 1);

#pragma unroll
    for (int ks = 0; ks < 8; ++ks) {
        uint32_t a0, a1, a2, a3;
        LDMATRIX_X4(a0, a1, a2, a3,
                    aBase + ((((2u * ks + aSel) << 4) ^ aXor)));
#pragma unroll
        for (int nt2 = 0; nt2 < 4; ++nt2) {
            const int n0 = nb + nt2 * 16;
            const int bRow = n0 + bRowOff;
            uint32_t baddr = sbase + S_E + bRow * 256
                           + ((((2u * ks + bSel) << 4) ^ ((uint32_t)(bRow & 7) << 4)));
            uint32_t b0, b1, b2, b3;
            LDMATRIX_X4(b0, b1, b2, b3, baddr);
            MMA_BF16(acc[nt2 * 2],     a0, a1, a2, a3, b0, b1);
            MMA_BF16(acc[nt2 * 2 + 1], a0, a1, a2, a3, b2, b3);
        }
    }
    __syncthreads();   // all warps done reading E before Dbuf overwrites it

    // ------------------------------------------------------------------
    // Phase 3a: fold D = acc + (hi+lo) + mean into Dbuf (aliases E)
    // ------------------------------------------------------------------
    {
        const int r1 = m0 + (lane >> 2);
        const int r2 = r1 + 8;
        const int cl = 2 * (lane & 3);
#pragma unroll
        for (int nt = 0; nt < 8; ++nt) {
            const int c = nb + nt * 8 + cl;
            const float m0c = Ms[c], m1c = Ms[c + 1];
            uint32_t o1 = tile_off(r1, c), o2 = tile_off(r2, c);
            float2 h1 = bfx2f(*(uint32_t*)(smem + S_A  + o1));
            float2 l1 = bfx2f(*(uint32_t*)(smem + S_AL + o1));
            float2 h2 = bfx2f(*(uint32_t*)(smem + S_A  + o2));
            float2 l2 = bfx2f(*(uint32_t*)(smem + S_AL + o2));
            *(float2*)&Db[r1 * DPAD + c] =
                make_float2(acc[nt][0] + h1.x + l1.x + m0c,
                            acc[nt][1] + h1.y + l1.y + m1c);
            *(float2*)&Db[r2 * DPAD + c] =
                make_float2(acc[nt][2] + h2.x + l2.x + m0c,
                            acc[nt][3] + h2.y + l2.y + m1c);
        }
    }
    __syncthreads();

    // ------------------------------------------------------------------
    // Phase 3b: coalesced epilogue: smooth = D; y_trans = y_obs - smooth
    // ------------------------------------------------------------------
    {
        const int J = lane;
#pragma unroll
        for (int it = 0; it < 8; ++it) {
            const int r = it * 8 + wid;
            float4 d4 = *(const float4*)&Db[r * DPAD + J * 4];
            const size_t base = ((size_t)(wb * TILE + r)) * CC;
            ((float4*)(out + base))[J] = d4;                      // smooth
            ((float4*)(out + base + 2 * DD))[J] =
                make_float4(yo[it].x - d4.x, yo[it].y - d4.y,
                            yo[it].z - d4.z, yo[it].w - d4.w);
        }
    }
}

// ---------------------------------------------------------------------------
extern "C" void kernel_launch(void* const* d_in, const int* in_sizes, int n_in,
                              void* d_out, int out_size) {
    const float* x    = (const float*)d_in[0];
    const float* kern = (const float*)d_in[1];
    float* out        = (float*)d_out;

    void* syncp = nullptr;
    cudaGetSymbolAddress(&syncp, g_sync);
    cudaMemsetAsync(syncp, 0, 256 * sizeof(unsigned), 0);

    cudaFuncSetAttribute(crosschan_fused_kernel,
                         cudaFuncAttributeMaxDynamicSharedMemorySize, S_TOTAL);
    crosschan_fused_kernel<<<NE_BLK + BB * (TT / TILE), 256, S_TOTAL>>>(x, kern, out);
}